// round 11
// baseline (speedup 1.0000x reference)
#include <cuda_runtime.h>
#include <math.h>
#include <stddef.h>

// Problem constants
#define BSZ 64
#define TT  3000
#define II  8
#define HH  128
#define GG  512      // 4*H
#define KREG 64      // hh-weight k's held in registers per gate
#define KS4  16      // (HH-KREG)/4 float4 groups per gate held in smem

// ---------------------------------------------------------------------------
// Scratch (device globals; no allocation anywhere)
// ---------------------------------------------------------------------------
__device__ float g_h0 [(size_t)BSZ * TT * HH];   // layer-0 hidden states
__device__ float g_xp1[(size_t)BSZ * TT * GG];   // layer-1 input projection (+biases)
__device__ float g_h1 [(size_t)BSZ * TT * HH];   // layer-1 hidden states
__device__ float g_y  [(size_t)BSZ * TT];        // MLP scalar output per (b,t)

__device__ __forceinline__ float sigf(float x) { return 1.0f / (1.0f + expf(-x)); }

// ---------------------------------------------------------------------------
// Fused LSTM recurrence. One CTA per batch element, 256 threads.
// Thread t owns gate rows g0 = t (i/f half) and g1 = t+256 (g/o half):
//   t <  128 : g0 = i_t,     g1 = g_t      (kept in registers for the cell update)
//   t >= 128 : g0 = f_{t-128}, g1 = o_{t-128} (written to fbuf/obuf)
// w_hh k=0..63 in registers, k=64..127 in smem as Ws4[k4][512] (conflict-free).
// LAYER==0: gates seeded by bias + w_ih0 (I=8) dot x[t] (prefetched).
// LAYER==1: gates seeded by precomputed g_xp1 (prefetched one step ahead).
// ---------------------------------------------------------------------------
template<int LAYER>
__global__ __launch_bounds__(256, 1) void lstm_kernel(
    const float* __restrict__ xin,     // LAYER0: x [B,T,8]; LAYER1: unused
    const float* __restrict__ w_ih,    // LAYER0: [512,8];   LAYER1: unused
    const float* __restrict__ w_hh,    // [512,128]
    const float* __restrict__ b_ih,    // LAYER0 only
    const float* __restrict__ b_hh)    // LAYER0 only
{
    extern __shared__ float smem[];
    float4* Ws4  = (float4*)smem;                 // [KS4][512] float4
    float*  hbuf = smem + KS4 * GG * 4;           // 128 floats
    float*  fbuf = hbuf + HH;                     // 128
    float*  obuf = fbuf + HH;                     // 128

    const int tid = threadIdx.x;
    const int b   = blockIdx.x;
    const int g0  = tid;
    const int g1  = tid + 256;

    const float* xsrc = (LAYER == 0) ? xin : g_xp1;
    float*       hout = (LAYER == 0) ? g_h0 : g_h1;

    // --- load recurrent weights: registers (k<KREG) + smem (k>=KREG) ---
    float wr0[KREG], wr1[KREG];
#pragma unroll
    for (int k = 0; k < KREG; k++) {
        wr0[k] = w_hh[g0 * HH + k];
        wr1[k] = w_hh[g1 * HH + k];
    }
    for (int i = tid; i < KS4 * GG; i += 256) {
        int kk = i >> 9;          // / 512
        int g  = i & (GG - 1);    // % 512
        Ws4[i] = *(const float4*)&w_hh[g * HH + KREG + kk * 4];
    }

    float bsum0 = 0.f, bsum1 = 0.f;
    float wi0[II], wi1[II];
    if (LAYER == 0) {
#pragma unroll
        for (int k = 0; k < II; k++) {
            wi0[k] = w_ih[g0 * II + k];
            wi1[k] = w_ih[g1 * II + k];
        }
        bsum0 = b_ih[g0] + b_hh[g0];
        bsum1 = b_ih[g1] + b_hh[g1];
    }

    if (tid < 32) ((float4*)hbuf)[tid] = make_float4(0.f, 0.f, 0.f, 0.f);
    float c = 0.f;

    // --- prefetch step-0 gate seeds ---
    float4 xa, xb;        // layer 0: 8 x-values
    float  p0 = 0.f, p1 = 0.f;  // layer 1: xp1 values for g0/g1
    if (LAYER == 0) {
        const float4* xp = (const float4*)(xsrc + (size_t)b * TT * II);
        xa = xp[0]; xb = xp[1];
    } else {
        const float* xp = xsrc + (size_t)b * TT * GG;
        p0 = xp[g0]; p1 = xp[g1];
    }
    __syncthreads();

    for (int s = 0; s < TT; s++) {
        float acc0, acc1;
        const int sn = (s + 1 < TT) ? s + 1 : s;  // clamped prefetch index

        if (LAYER == 0) {
            acc0 = bsum0; acc1 = bsum1;
            float xv[II];
            *(float4*)&xv[0] = xa; *(float4*)&xv[4] = xb;
#pragma unroll
            for (int k = 0; k < II; k++) {
                acc0 = fmaf(wi0[k], xv[k], acc0);
                acc1 = fmaf(wi1[k], xv[k], acc1);
            }
            const float4* xp = (const float4*)(xsrc + ((size_t)b * TT + sn) * II);
            xa = xp[0]; xb = xp[1];               // prefetch next step
        } else {
            acc0 = p0; acc1 = p1;
            const float* xp = xsrc + ((size_t)b * TT + sn) * GG;
            p0 = xp[g0]; p1 = xp[g1];             // prefetch next step
        }

        // --- gates += w_hh . h  (register half + smem half) ---
        const float4* h4 = (const float4*)hbuf;
#pragma unroll
        for (int kk = 0; kk < KREG / 4; kk++) {
            float4 hv = h4[kk];
            acc0 = fmaf(wr0[4*kk+0], hv.x, acc0);
            acc0 = fmaf(wr0[4*kk+1], hv.y, acc0);
            acc0 = fmaf(wr0[4*kk+2], hv.z, acc0);
            acc0 = fmaf(wr0[4*kk+3], hv.w, acc0);
            acc1 = fmaf(wr1[4*kk+0], hv.x, acc1);
            acc1 = fmaf(wr1[4*kk+1], hv.y, acc1);
            acc1 = fmaf(wr1[4*kk+2], hv.z, acc1);
            acc1 = fmaf(wr1[4*kk+3], hv.w, acc1);
        }
#pragma unroll
        for (int kk = 0; kk < KS4; kk++) {
            float4 hv = h4[KREG / 4 + kk];
            float4 w0 = Ws4[kk * GG + g0];
            float4 w1 = Ws4[kk * GG + g1];
            acc0 = fmaf(w0.x, hv.x, acc0);
            acc0 = fmaf(w0.y, hv.y, acc0);
            acc0 = fmaf(w0.z, hv.z, acc0);
            acc0 = fmaf(w0.w, hv.w, acc0);
            acc1 = fmaf(w1.x, hv.x, acc1);
            acc1 = fmaf(w1.y, hv.y, acc1);
            acc1 = fmaf(w1.z, hv.z, acc1);
            acc1 = fmaf(w1.w, hv.w, acc1);
        }

        if (tid >= 128) { fbuf[tid - 128] = acc0; obuf[tid - 128] = acc1; }
        __syncthreads();

        if (tid < 128) {
            float sf = sigf(fbuf[tid]);
            float so = sigf(obuf[tid]);
            float si = sigf(acc0);          // i gate (own register)
            float tg = tanhf(acc1);         // g gate (own register)
            c = fmaf(sf, c, si * tg);
            float h = so * tanhf(c);
            hbuf[tid] = h;
            hout[((size_t)b * TT + s) * HH + tid] = h;
        }
        __syncthreads();
    }
}

// ---------------------------------------------------------------------------
// xp1[r][g] = sum_k h0[r][k] * w_ih1[g][k] + b_ih1[g] + b_hh1[g]
// M=192000, K=128, N=512.  128x128 tiles, 8x8 micro-tiles, k-fastest float4
// dot-product layout (both operands stored row-major as float4, rows padded
// to 33 float4 for conflict-free strided reads).
// ---------------------------------------------------------------------------
__global__ __launch_bounds__(256, 1) void gemm_xp1_kernel(
    const float* __restrict__ w_ih1,
    const float* __restrict__ b_ih1,
    const float* __restrict__ b_hh1)
{
    extern __shared__ float smem[];
    float4* As = (float4*)smem;       // [128][33]
    float4* Bs = As + 128 * 33;       // [128][33]

    const int tid = threadIdx.x;
    const int ty = tid >> 4;          // 0..15
    const int tx = tid & 15;          // 0..15
    const int rbase = blockIdx.x * 128;
    const int gbase = blockIdx.y * 128;

    const float4* h04 = (const float4*)g_h0;
    const float4* w4  = (const float4*)w_ih1;
    for (int i = tid; i < 128 * 32; i += 256) {
        int r = i >> 5, k4 = i & 31;
        As[r * 33 + k4] = h04[(size_t)(rbase + r) * 32 + k4];
    }
    for (int i = tid; i < 128 * 32; i += 256) {
        int g = i >> 5, k4 = i & 31;
        Bs[g * 33 + k4] = w4[(size_t)(gbase + g) * 32 + k4];
    }
    __syncthreads();

    float acc[8][8];
#pragma unroll
    for (int i = 0; i < 8; i++)
#pragma unroll
        for (int j = 0; j < 8; j++) acc[i][j] = 0.f;

    for (int k4 = 0; k4 < 32; k4++) {
        float4 av[8], bv[8];
#pragma unroll
        for (int i = 0; i < 8; i++) av[i] = As[(ty + 16 * i) * 33 + k4];
#pragma unroll
        for (int j = 0; j < 8; j++) bv[j] = Bs[(tx + 16 * j) * 33 + k4];
#pragma unroll
        for (int i = 0; i < 8; i++)
#pragma unroll
            for (int j = 0; j < 8; j++) {
                acc[i][j] = fmaf(av[i].x, bv[j].x, acc[i][j]);
                acc[i][j] = fmaf(av[i].y, bv[j].y, acc[i][j]);
                acc[i][j] = fmaf(av[i].z, bv[j].z, acc[i][j]);
                acc[i][j] = fmaf(av[i].w, bv[j].w, acc[i][j]);
            }
    }

    float bb[8];
#pragma unroll
    for (int j = 0; j < 8; j++) {
        int g = gbase + tx + 16 * j;
        bb[j] = b_ih1[g] + b_hh1[g];
    }
#pragma unroll
    for (int i = 0; i < 8; i++) {
        size_t row = (size_t)(rbase + ty + 16 * i);
#pragma unroll
        for (int j = 0; j < 8; j++)
            g_xp1[row * GG + gbase + tx + 16 * j] = acc[i][j] + bb[j];
    }
}

// ---------------------------------------------------------------------------
// MLP head: y = fc3(relu(fc2(relu(fc1(h1))))). 64 positions / block,
// one thread per position, h tile in padded smem (stride 129 -> no conflicts).
// ---------------------------------------------------------------------------
__global__ __launch_bounds__(64) void mlp_kernel(
    const float* __restrict__ fc1w, const float* __restrict__ fc1b,
    const float* __restrict__ fc2w, const float* __restrict__ fc2b,
    const float* __restrict__ fc3w, const float* __restrict__ fc3b)
{
    __shared__ float hs[64 * 129];
    __shared__ float w1[16 * 128];
    __shared__ float b1s[16], w2s[64], b2s[4], w3s[4], b3s[1];

    const int tid = threadIdx.x;
    const size_t pos0 = (size_t)blockIdx.x * 64;

    const float4* h14 = (const float4*)g_h1;
    for (int i = tid; i < 64 * 32; i += 64) {
        int r = i >> 5, k4 = i & 31;
        float4 v = h14[(pos0 + r) * 32 + k4];
        float* d = &hs[r * 129 + k4 * 4];
        d[0] = v.x; d[1] = v.y; d[2] = v.z; d[3] = v.w;
    }
    for (int i = tid; i < 2048; i += 64) w1[i] = fc1w[i];
    if (tid < 16) b1s[tid] = fc1b[tid];
    if (tid < 64) w2s[tid] = fc2w[tid];
    if (tid < 4)  { b2s[tid] = fc2b[tid]; w3s[tid] = fc3w[tid]; }
    if (tid == 0) b3s[0] = fc3b[0];
    __syncthreads();

    float o1[16];
#pragma unroll
    for (int i = 0; i < 16; i++) o1[i] = b1s[i];
    const float* hp = &hs[tid * 129];
    for (int k = 0; k < 128; k++) {
        float hv = hp[k];
#pragma unroll
        for (int i = 0; i < 16; i++) o1[i] = fmaf(w1[i * 128 + k], hv, o1[i]);
    }
#pragma unroll
    for (int i = 0; i < 16; i++) o1[i] = fmaxf(o1[i], 0.f);

    float o2[4];
#pragma unroll
    for (int j = 0; j < 4; j++) {
        float s = b2s[j];
#pragma unroll
        for (int i = 0; i < 16; i++) s = fmaf(w2s[j * 16 + i], o1[i], s);
        o2[j] = fmaxf(s, 0.f);
    }
    float yv = b3s[0];
#pragma unroll
    for (int j = 0; j < 4; j++) yv = fmaf(w3s[j], o2[j], yv);
    g_y[pos0 + tid] = yv;
}

// ---------------------------------------------------------------------------
// Double finite-difference: out = phi @ (phi @ y) per batch column.
// phi entries (pre-divided by dt=0.02) are exactly {±25, ±75, ±100} in fp32.
// ---------------------------------------------------------------------------
__global__ __launch_bounds__(256) void fd_kernel(float* __restrict__ out)
{
    __shared__ float ys[TT];
    __shared__ float d1[TT];
    const int b = blockIdx.x, tid = threadIdx.x;
    const float* yb = g_y + (size_t)b * TT;

    for (int t = tid; t < TT; t += 256) ys[t] = yb[t];
    __syncthreads();
    for (int t = tid; t < TT; t += 256) {
        float v;
        if (t == 0)          v = -75.f * ys[0] + 100.f * ys[1] - 25.f * ys[2];
        else if (t == TT - 1) v = 25.f * ys[TT-3] - 100.f * ys[TT-2] + 75.f * ys[TT-1];
        else                 v = 25.f * (ys[t + 1] - ys[t - 1]);
        d1[t] = v;
    }
    __syncthreads();
    for (int t = tid; t < TT; t += 256) {
        float v;
        if (t == 0)          v = -75.f * d1[0] + 100.f * d1[1] - 25.f * d1[2];
        else if (t == TT - 1) v = 25.f * d1[TT-3] - 100.f * d1[TT-2] + 75.f * d1[TT-1];
        else                 v = 25.f * (d1[t + 1] - d1[t - 1]);
        out[(size_t)b * TT + t] = v;
    }
}

// ---------------------------------------------------------------------------
// Launch
// ---------------------------------------------------------------------------
extern "C" void kernel_launch(void* const* d_in, const int* in_sizes, int n_in,
                              void* d_out, int out_size)
{
    const float* x     = (const float*)d_in[0];
    const float* w_ih0 = (const float*)d_in[1];
    const float* w_hh0 = (const float*)d_in[2];
    const float* b_ih0 = (const float*)d_in[3];
    const float* b_hh0 = (const float*)d_in[4];
    const float* w_ih1 = (const float*)d_in[5];
    const float* w_hh1 = (const float*)d_in[6];
    const float* b_ih1 = (const float*)d_in[7];
    const float* b_hh1 = (const float*)d_in[8];
    const float* fc1w  = (const float*)d_in[9];
    const float* fc1b  = (const float*)d_in[10];
    const float* fc2w  = (const float*)d_in[11];
    const float* fc2b  = (const float*)d_in[12];
    const float* fc3w  = (const float*)d_in[13];
    const float* fc3b  = (const float*)d_in[14];
    float* out = (float*)d_out;

    const int LSTM_SMEM = (KS4 * GG * 4 + 3 * HH) * (int)sizeof(float);  // 132608 B
    const int GEMM_SMEM = 2 * 128 * 33 * (int)sizeof(float4);            // 135168 B

    // Sticky attributes; idempotent (no static guards needed).
    cudaFuncSetAttribute(lstm_kernel<0>, cudaFuncAttributeMaxDynamicSharedMemorySize, LSTM_SMEM);
    cudaFuncSetAttribute(lstm_kernel<1>, cudaFuncAttributeMaxDynamicSharedMemorySize, LSTM_SMEM);
    cudaFuncSetAttribute(gemm_xp1_kernel, cudaFuncAttributeMaxDynamicSharedMemorySize, GEMM_SMEM);

    // 1. Layer-0 LSTM (folds the I=8 input projection) -> g_h0
    lstm_kernel<0><<<BSZ, 256, LSTM_SMEM>>>(x, w_ih0, w_hh0, b_ih0, b_hh0);
    // 2. Layer-1 input projection (+biases) -> g_xp1
    gemm_xp1_kernel<<<dim3((BSZ * TT) / 128, GG / 128), 256, GEMM_SMEM>>>(w_ih1, b_ih1, b_hh1);
    // 3. Layer-1 LSTM -> g_h1
    lstm_kernel<1><<<BSZ, 256, LSTM_SMEM>>>(nullptr, nullptr, w_hh1, nullptr, nullptr);
    // 4. MLP head -> g_y
    mlp_kernel<<<(BSZ * TT) / 64, 64>>>(fc1w, fc1b, fc2w, fc2b, fc3w, fc3b);
    // 5. Double FD stencil -> out
    fd_kernel<<<BSZ, 256>>>(out);
}

// round 12
// speedup vs baseline: 1.3796x; 1.3796x over previous
#include <cuda_runtime.h>
#include <math.h>
#include <stddef.h>

typedef unsigned long long ull;

// Problem constants
#define BSZ 64
#define TT  3000
#define II  8
#define HH  128
#define GG  512      // 4*H
#define KREG 96      // hh-weight k's held in registers per gate
#define KRP  48      // register k-PAIRS per gate (KREG/2)
#define KS4  8       // (HH-KREG)/4 float4 groups per gate held in smem

// ---------------------------------------------------------------------------
// Scratch (device globals; no allocation anywhere)
// ---------------------------------------------------------------------------
__device__ float g_h0 [(size_t)BSZ * TT * HH];   // layer-0 hidden states
__device__ float g_xp1[(size_t)BSZ * TT * GG];   // layer-1 input projection (+biases)
__device__ float g_h1 [(size_t)BSZ * TT * HH];   // layer-1 hidden states
__device__ float g_y  [(size_t)BSZ * TT];        // MLP scalar output per (b,t)

__device__ __forceinline__ float sigf(float x) { return 1.0f / (1.0f + expf(-x)); }

// Packed fp32x2 FMA (sm_100+; ptxas never auto-fuses this)
__device__ __forceinline__ void fma2(ull& d, ull a, ull b) {
    asm("fma.rn.f32x2 %0, %1, %2, %0;" : "+l"(d) : "l"(a), "l"(b));
}
__device__ __forceinline__ ull pack2(float lo, float hi) {
    ull r; asm("mov.b64 %0, {%1, %2};" : "=l"(r) : "f"(lo), "f"(hi)); return r;
}
__device__ __forceinline__ float hsum2(ull v) {
    float lo, hi; asm("mov.b64 {%0, %1}, %2;" : "=f"(lo), "=f"(hi) : "l"(v));
    return lo + hi;
}

// ---------------------------------------------------------------------------
// Fused LSTM recurrence. One CTA per batch element, 256 threads.
// Thread t owns gate rows g0 = t and g1 = t + 256:
//   t <  128 : g0 = i_t,       g1 = g_t       (activations kept in registers)
//   t >= 128 : g0 = f_{t-128}, g1 = o_{t-128} (sigmoid applied, written to smem)
// w_hh k=0..95 in registers as 48 b64 pairs/gate; k=96..127 in smem
// as Ws4[kk][512] float4 (conflict-free 16B strided reads).
// Dot products run on the packed f32x2 pipe (even/odd-k partial sums).
// ---------------------------------------------------------------------------
template<int LAYER>
__global__ __launch_bounds__(256, 1) void lstm_kernel(
    const float* __restrict__ xin,     // LAYER0: x [B,T,8]; LAYER1: unused
    const float* __restrict__ w_ih,    // LAYER0: [512,8];   LAYER1: unused
    const float* __restrict__ w_hh,    // [512,128]
    const float* __restrict__ b_ih,    // LAYER0 only
    const float* __restrict__ b_hh)    // LAYER0 only
{
    extern __shared__ float smem[];
    float4* Ws4  = (float4*)smem;                 // [KS4][512] float4 = 64 KB
    float*  hbuf = smem + KS4 * GG * 4;           // 128 floats
    float*  fbuf = hbuf + HH;                     // 128 (sigmoid(f))
    float*  obuf = fbuf + HH;                     // 128 (sigmoid(o))

    const int tid = threadIdx.x;
    const int b   = blockIdx.x;
    const int g0  = tid;
    const int g1  = tid + 256;

    const float* xsrc = (LAYER == 0) ? xin : g_xp1;
    float*       hout = (LAYER == 0) ? g_h0 : g_h1;

    // --- recurrent weights: register pairs (k<KREG) + smem (k>=KREG) ---
    ull wr0[KRP], wr1[KRP];
    {
        const ull* w0p = (const ull*)(w_hh + (size_t)g0 * HH);
        const ull* w1p = (const ull*)(w_hh + (size_t)g1 * HH);
#pragma unroll
        for (int k = 0; k < KRP; k++) { wr0[k] = w0p[k]; wr1[k] = w1p[k]; }
    }
    for (int i = tid; i < KS4 * GG; i += 256) {
        int kk = i >> 9;          // / 512
        int g  = i & (GG - 1);    // % 512
        Ws4[i] = *(const float4*)&w_hh[g * HH + KREG + kk * 4];
    }

    float bsum0 = 0.f, bsum1 = 0.f;
    float wi0[II], wi1[II];
    if (LAYER == 0) {
#pragma unroll
        for (int k = 0; k < II; k++) {
            wi0[k] = w_ih[g0 * II + k];
            wi1[k] = w_ih[g1 * II + k];
        }
        bsum0 = b_ih[g0] + b_hh[g0];
        bsum1 = b_ih[g1] + b_hh[g1];
    }

    if (tid < 32) ((float4*)hbuf)[tid] = make_float4(0.f, 0.f, 0.f, 0.f);
    float c = 0.f;

    // --- prefetch step-0 gate seeds ---
    float4 xa, xb;              // layer 0: 8 x-values
    float  p0 = 0.f, p1 = 0.f;  // layer 1: xp1 values for g0/g1
    if (LAYER == 0) {
        const float4* xp = (const float4*)(xsrc + (size_t)b * TT * II);
        xa = xp[0]; xb = xp[1];
    } else {
        const float* xp = xsrc + (size_t)b * TT * GG;
        p0 = xp[g0]; p1 = xp[g1];
    }
    __syncthreads();

    for (int s = 0; s < TT; s++) {
        float seed0, seed1;
        const int sn = (s + 1 < TT) ? s + 1 : s;  // clamped prefetch index

        if (LAYER == 0) {
            seed0 = bsum0; seed1 = bsum1;
            float xv[II];
            *(float4*)&xv[0] = xa; *(float4*)&xv[4] = xb;
#pragma unroll
            for (int k = 0; k < II; k++) {
                seed0 = fmaf(wi0[k], xv[k], seed0);
                seed1 = fmaf(wi1[k], xv[k], seed1);
            }
            const float4* xp = (const float4*)(xsrc + ((size_t)b * TT + sn) * II);
            xa = xp[0]; xb = xp[1];               // prefetch next step
        } else {
            seed0 = p0; seed1 = p1;
            const float* xp = xsrc + ((size_t)b * TT + sn) * GG;
            p0 = xp[g0]; p1 = xp[g1];             // prefetch next step
        }

        // --- gates += w_hh . h : f32x2 packed dot (even/odd-k partial sums) ---
        ull acc2_0 = pack2(seed0, 0.f);
        ull acc2_1 = pack2(seed1, 0.f);
        const ulonglong2* hq = (const ulonglong2*)hbuf;  // 16B loads, 2 pairs each
#pragma unroll
        for (int k = 0; k < KRP / 2; k++) {              // h floats [0, 96)
            ulonglong2 hp = hq[k];
            fma2(acc2_0, wr0[2*k],   hp.x);
            fma2(acc2_0, wr0[2*k+1], hp.y);
            fma2(acc2_1, wr1[2*k],   hp.x);
            fma2(acc2_1, wr1[2*k+1], hp.y);
        }
        const ulonglong2* Wq = (const ulonglong2*)Ws4;
#pragma unroll
        for (int kk = 0; kk < KS4; kk++) {               // h floats [96, 128)
            ulonglong2 hp = hq[KRP / 2 + kk];
            ulonglong2 w0 = Wq[kk * GG + g0];
            ulonglong2 w1 = Wq[kk * GG + g1];
            fma2(acc2_0, w0.x, hp.x);
            fma2(acc2_0, w0.y, hp.y);
            fma2(acc2_1, w1.x, hp.x);
            fma2(acc2_1, w1.y, hp.y);
        }
        float acc0 = hsum2(acc2_0);
        float acc1 = hsum2(acc2_1);

        // --- activations: balanced across all 8 warps ---
        float a_i = 0.f, a_g = 0.f;
        if (tid < 128) {
            a_i = sigf(acc0);                 // i gate
            a_g = tanhf(acc1);                // g gate
        } else {
            fbuf[tid - 128] = sigf(acc0);     // f gate, pre-activated
            obuf[tid - 128] = sigf(acc1);     // o gate, pre-activated
        }
        __syncthreads();

        if (tid < 128) {
            c = fmaf(fbuf[tid], c, a_i * a_g);
            float h = obuf[tid] * tanhf(c);
            hbuf[tid] = h;
            hout[((size_t)b * TT + s) * HH + tid] = h;
        }
        __syncthreads();
    }
}

// ---------------------------------------------------------------------------
// xp1[r][g] = sum_k h0[r][k] * w_ih1[g][k] + b_ih1[g] + b_hh1[g]
// M=192000, K=128, N=512.  128x128 tiles, 8x8 micro-tiles, k-fastest float4
// dot-product layout (rows padded to 33 float4 for conflict-free reads).
// ---------------------------------------------------------------------------
__global__ __launch_bounds__(256, 1) void gemm_xp1_kernel(
    const float* __restrict__ w_ih1,
    const float* __restrict__ b_ih1,
    const float* __restrict__ b_hh1)
{
    extern __shared__ float smem[];
    float4* As = (float4*)smem;       // [128][33]
    float4* Bs = As + 128 * 33;       // [128][33]

    const int tid = threadIdx.x;
    const int ty = tid >> 4;          // 0..15
    const int tx = tid & 15;          // 0..15
    const int rbase = blockIdx.x * 128;
    const int gbase = blockIdx.y * 128;

    const float4* h04 = (const float4*)g_h0;
    const float4* w4  = (const float4*)w_ih1;
    for (int i = tid; i < 128 * 32; i += 256) {
        int r = i >> 5, k4 = i & 31;
        As[r * 33 + k4] = h04[(size_t)(rbase + r) * 32 + k4];
    }
    for (int i = tid; i < 128 * 32; i += 256) {
        int g = i >> 5, k4 = i & 31;
        Bs[g * 33 + k4] = w4[(size_t)(gbase + g) * 32 + k4];
    }
    __syncthreads();

    float acc[8][8];
#pragma unroll
    for (int i = 0; i < 8; i++)
#pragma unroll
        for (int j = 0; j < 8; j++) acc[i][j] = 0.f;

    for (int k4 = 0; k4 < 32; k4++) {
        float4 av[8], bv[8];
#pragma unroll
        for (int i = 0; i < 8; i++) av[i] = As[(ty + 16 * i) * 33 + k4];
#pragma unroll
        for (int j = 0; j < 8; j++) bv[j] = Bs[(tx + 16 * j) * 33 + k4];
#pragma unroll
        for (int i = 0; i < 8; i++)
#pragma unroll
            for (int j = 0; j < 8; j++) {
                acc[i][j] = fmaf(av[i].x, bv[j].x, acc[i][j]);
                acc[i][j] = fmaf(av[i].y, bv[j].y, acc[i][j]);
                acc[i][j] = fmaf(av[i].z, bv[j].z, acc[i][j]);
                acc[i][j] = fmaf(av[i].w, bv[j].w, acc[i][j]);
            }
    }

    float bb[8];
#pragma unroll
    for (int j = 0; j < 8; j++) {
        int g = gbase + tx + 16 * j;
        bb[j] = b_ih1[g] + b_hh1[g];
    }
#pragma unroll
    for (int i = 0; i < 8; i++) {
        size_t row = (size_t)(rbase + ty + 16 * i);
#pragma unroll
        for (int j = 0; j < 8; j++)
            g_xp1[row * GG + gbase + tx + 16 * j] = acc[i][j] + bb[j];
    }
}

// ---------------------------------------------------------------------------
// MLP head: y = fc3(relu(fc2(relu(fc1(h1))))). 64 positions / block.
// ---------------------------------------------------------------------------
__global__ __launch_bounds__(64) void mlp_kernel(
    const float* __restrict__ fc1w, const float* __restrict__ fc1b,
    const float* __restrict__ fc2w, const float* __restrict__ fc2b,
    const float* __restrict__ fc3w, const float* __restrict__ fc3b)
{
    __shared__ float hs[64 * 129];
    __shared__ float w1[16 * 128];
    __shared__ float b1s[16], w2s[64], b2s[4], w3s[4], b3s[1];

    const int tid = threadIdx.x;
    const size_t pos0 = (size_t)blockIdx.x * 64;

    const float4* h14 = (const float4*)g_h1;
    for (int i = tid; i < 64 * 32; i += 64) {
        int r = i >> 5, k4 = i & 31;
        float4 v = h14[(pos0 + r) * 32 + k4];
        float* d = &hs[r * 129 + k4 * 4];
        d[0] = v.x; d[1] = v.y; d[2] = v.z; d[3] = v.w;
    }
    for (int i = tid; i < 2048; i += 64) w1[i] = fc1w[i];
    if (tid < 16) b1s[tid] = fc1b[tid];
    if (tid < 64) w2s[tid] = fc2w[tid];
    if (tid < 4)  { b2s[tid] = fc2b[tid]; w3s[tid] = fc3w[tid]; }
    if (tid == 0) b3s[0] = fc3b[0];
    __syncthreads();

    float o1[16];
#pragma unroll
    for (int i = 0; i < 16; i++) o1[i] = b1s[i];
    const float* hp = &hs[tid * 129];
    for (int k = 0; k < 128; k++) {
        float hv = hp[k];
#pragma unroll
        for (int i = 0; i < 16; i++) o1[i] = fmaf(w1[i * 128 + k], hv, o1[i]);
    }
#pragma unroll
    for (int i = 0; i < 16; i++) o1[i] = fmaxf(o1[i], 0.f);

    float o2[4];
#pragma unroll
    for (int j = 0; j < 4; j++) {
        float s = b2s[j];
#pragma unroll
        for (int i = 0; i < 16; i++) s = fmaf(w2s[j * 16 + i], o1[i], s);
        o2[j] = fmaxf(s, 0.f);
    }
    float yv = b3s[0];
#pragma unroll
    for (int j = 0; j < 4; j++) yv = fmaf(w3s[j], o2[j], yv);
    g_y[pos0 + tid] = yv;
}

// ---------------------------------------------------------------------------
// Double finite-difference: out = phi @ (phi @ y) per batch column.
// phi entries (pre-divided by dt=0.02) are exactly {±25, ±75, ±100} in fp32.
// ---------------------------------------------------------------------------
__global__ __launch_bounds__(256) void fd_kernel(float* __restrict__ out)
{
    __shared__ float ys[TT];
    __shared__ float d1[TT];
    const int b = blockIdx.x, tid = threadIdx.x;
    const float* yb = g_y + (size_t)b * TT;

    for (int t = tid; t < TT; t += 256) ys[t] = yb[t];
    __syncthreads();
    for (int t = tid; t < TT; t += 256) {
        float v;
        if (t == 0)          v = -75.f * ys[0] + 100.f * ys[1] - 25.f * ys[2];
        else if (t == TT - 1) v = 25.f * ys[TT-3] - 100.f * ys[TT-2] + 75.f * ys[TT-1];
        else                 v = 25.f * (ys[t + 1] - ys[t - 1]);
        d1[t] = v;
    }
    __syncthreads();
    for (int t = tid; t < TT; t += 256) {
        float v;
        if (t == 0)          v = -75.f * d1[0] + 100.f * d1[1] - 25.f * d1[2];
        else if (t == TT - 1) v = 25.f * d1[TT-3] - 100.f * d1[TT-2] + 75.f * d1[TT-1];
        else                 v = 25.f * (d1[t + 1] - d1[t - 1]);
        out[(size_t)b * TT + t] = v;
    }
}

// ---------------------------------------------------------------------------
// Launch
// ---------------------------------------------------------------------------
extern "C" void kernel_launch(void* const* d_in, const int* in_sizes, int n_in,
                              void* d_out, int out_size)
{
    const float* x     = (const float*)d_in[0];
    const float* w_ih0 = (const float*)d_in[1];
    const float* w_hh0 = (const float*)d_in[2];
    const float* b_ih0 = (const float*)d_in[3];
    const float* b_hh0 = (const float*)d_in[4];
    const float* w_ih1 = (const float*)d_in[5];
    const float* w_hh1 = (const float*)d_in[6];
    const float* b_ih1 = (const float*)d_in[7];
    const float* b_hh1 = (const float*)d_in[8];
    const float* fc1w  = (const float*)d_in[9];
    const float* fc1b  = (const float*)d_in[10];
    const float* fc2w  = (const float*)d_in[11];
    const float* fc2b  = (const float*)d_in[12];
    const float* fc3w  = (const float*)d_in[13];
    const float* fc3b  = (const float*)d_in[14];
    float* out = (float*)d_out;

    const int LSTM_SMEM = (KS4 * GG * 4 + 3 * HH) * (int)sizeof(float);  // 67072 B
    const int GEMM_SMEM = 2 * 128 * 33 * (int)sizeof(float4);            // 135168 B

    // Sticky attributes; idempotent (no static guards needed).
    cudaFuncSetAttribute(lstm_kernel<0>, cudaFuncAttributeMaxDynamicSharedMemorySize, LSTM_SMEM);
    cudaFuncSetAttribute(lstm_kernel<1>, cudaFuncAttributeMaxDynamicSharedMemorySize, LSTM_SMEM);
    cudaFuncSetAttribute(gemm_xp1_kernel, cudaFuncAttributeMaxDynamicSharedMemorySize, GEMM_SMEM);

    // 1. Layer-0 LSTM (folds the I=8 input projection) -> g_h0
    lstm_kernel<0><<<BSZ, 256, LSTM_SMEM>>>(x, w_ih0, w_hh0, b_ih0, b_hh0);
    // 2. Layer-1 input projection (+biases) -> g_xp1
    gemm_xp1_kernel<<<dim3((BSZ * TT) / 128, GG / 128), 256, GEMM_SMEM>>>(w_ih1, b_ih1, b_hh1);
    // 3. Layer-1 LSTM -> g_h1
    lstm_kernel<1><<<BSZ, 256, LSTM_SMEM>>>(nullptr, nullptr, w_hh1, nullptr, nullptr);
    // 4. MLP head -> g_y
    mlp_kernel<<<(BSZ * TT) / 64, 64>>>(fc1w, fc1b, fc2w, fc2b, fc3w, fc3b);
    // 5. Double FD stencil -> out
    fd_kernel<<<BSZ, 256>>>(out);
}